// round 3
// baseline (speedup 1.0000x reference)
#include <cuda_runtime.h>

#define N_NODES 8192
#define E_EDGES 262144
#define IN_DIM  512
#define HID_DIM 256
#define Z_DIM   64

typedef unsigned long long ull;

// Scratch (device globals: allocation-free)
__device__ float g_h0[N_NODES * HID_DIM];   // x @ W1
__device__ float g_h [N_NODES * HID_DIM];   // relu(spmm(h0))
__device__ float g_p [N_NODES * Z_DIM];     // h @ W2
__device__ int   g_rowptr[N_NODES + 1];

// ---------------------------------------------------------------------------
// Packed f32x2 helpers
// ---------------------------------------------------------------------------
__device__ __forceinline__ ull pack2(float x, float y) {
    ull r; asm("mov.b64 %0, {%1, %2};" : "=l"(r) : "f"(x), "f"(y)); return r;
}
__device__ __forceinline__ ull dup2(float x) { return pack2(x, x); }
__device__ __forceinline__ ull fma2(ull a, ull b, ull c) {
    ull d; asm("fma.rn.f32x2 %0, %1, %2, %3;" : "=l"(d) : "l"(a), "l"(b), "l"(c));
    return d;
}
__device__ __forceinline__ float2 unpack2(ull v) {
    float2 f; asm("mov.b64 {%0, %1}, %2;" : "=f"(f.x), "=f"(f.y) : "l"(v)); return f;
}

// ---------------------------------------------------------------------------
// CSR row pointer from sorted edge_row
// ---------------------------------------------------------------------------
__global__ void rowptr_kernel(const int* __restrict__ er) {
    int i = blockIdx.x * blockDim.x + threadIdx.x;
    if (i > N_NODES) return;
    int lo = 0, hi = E_EDGES;
    while (lo < hi) {
        int mid = (lo + hi) >> 1;
        if (er[mid] < i) lo = mid + 1; else hi = mid;
    }
    g_rowptr[i] = lo;
}

// ---------------------------------------------------------------------------
// Tiled fp32 GEMM, register-prefetch double buffering. TM=TN=4, f32x2 inner.
// Requires NT == (BM/4)*(BN/4), K % BK == 0.
// ---------------------------------------------------------------------------
template<int BM, int BN, int BK, int NT>
__global__ __launch_bounds__(NT) void sgemm_nn(
    const float* __restrict__ A, const float* __restrict__ B,
    float* __restrict__ C, int M, int K, int N)
{
    __shared__ float As[BK][BM + 4];
    __shared__ float Bs[BK][BN];
    const int LA = BM * BK / NT;
    const int LB = BK * BN / NT;
    const int tid = threadIdx.x;
    const int tx = tid % (BN / 4);
    const int ty = tid / (BN / 4);
    const int mbase = blockIdx.y * BM;
    const int nbase = blockIdx.x * BN;

    ull acc[4][2] = {};
    float apf[LA], bpf[LB];

    // preload k-tile 0
    #pragma unroll
    for (int u = 0; u < LA; ++u) {
        int idx = tid + u * NT; int m = idx / BK, k = idx % BK;
        apf[u] = A[(size_t)(mbase + m) * K + k];
    }
    #pragma unroll
    for (int u = 0; u < LB; ++u) {
        int idx = tid + u * NT; int k = idx / BN, n = idx % BN;
        bpf[u] = B[(size_t)k * N + nbase + n];
    }

    for (int kk = 0; kk < K; kk += BK) {
        #pragma unroll
        for (int u = 0; u < LA; ++u) {
            int idx = tid + u * NT; int m = idx / BK, k = idx % BK;
            As[k][m] = apf[u];
        }
        #pragma unroll
        for (int u = 0; u < LB; ++u) {
            int idx = tid + u * NT; int k = idx / BN, n = idx % BN;
            Bs[k][n] = bpf[u];
        }
        __syncthreads();

        if (kk + BK < K) {
            #pragma unroll
            for (int u = 0; u < LA; ++u) {
                int idx = tid + u * NT; int m = idx / BK, k = idx % BK;
                apf[u] = A[(size_t)(mbase + m) * K + kk + BK + k];
            }
            #pragma unroll
            for (int u = 0; u < LB; ++u) {
                int idx = tid + u * NT; int k = idx / BN, n = idx % BN;
                bpf[u] = B[(size_t)(kk + BK + k) * N + nbase + n];
            }
        }

        #pragma unroll
        for (int k = 0; k < BK; ++k) {
            float4 a4 = *(const float4*)&As[k][ty * 4];
            float4 b4 = *(const float4*)&Bs[k][tx * 4];
            ull b2[2] = { pack2(b4.x, b4.y), pack2(b4.z, b4.w) };
            float a[4] = { a4.x, a4.y, a4.z, a4.w };
            #pragma unroll
            for (int i = 0; i < 4; ++i) {
                ull ad = dup2(a[i]);
                acc[i][0] = fma2(ad, b2[0], acc[i][0]);
                acc[i][1] = fma2(ad, b2[1], acc[i][1]);
            }
        }
        __syncthreads();
    }

    #pragma unroll
    for (int i = 0; i < 4; ++i) {
        float2 c0 = unpack2(acc[i][0]);
        float2 c1 = unpack2(acc[i][1]);
        size_t off = (size_t)(mbase + ty * 4 + i) * N + nbase + tx * 4;
        *(float4*)&C[off] = make_float4(c0.x, c0.y, c1.x, c1.y);
    }
}

// ---------------------------------------------------------------------------
// SpMM, float4 lanes: out[r,4d..4d+3] = sum_e w[e] * hin[col[e], 4d..4d+3]
// blockDim.x = D/4 lanes, blockDim.y rows per block.
// ---------------------------------------------------------------------------
template<int D, bool RELU>
__global__ void spmm_kernel(const float* __restrict__ hin,
                            const int*   __restrict__ col,
                            const float* __restrict__ wgt,
                            float* __restrict__ hout)
{
    int row = blockIdx.x * blockDim.y + threadIdx.y;
    int d4 = threadIdx.x * 4;
    int s = g_rowptr[row];
    int e = g_rowptr[row + 1];
    float ax = 0.f, ay = 0.f, az = 0.f, aw = 0.f;
    int i = s;
    for (; i + 4 <= e; i += 4) {
        int   c0 = col[i+0], c1 = col[i+1], c2 = col[i+2], c3 = col[i+3];
        float w0 = wgt[i+0], w1 = wgt[i+1], w2 = wgt[i+2], w3 = wgt[i+3];
        float4 v0 = *(const float4*)&hin[(size_t)c0 * D + d4];
        float4 v1 = *(const float4*)&hin[(size_t)c1 * D + d4];
        float4 v2 = *(const float4*)&hin[(size_t)c2 * D + d4];
        float4 v3 = *(const float4*)&hin[(size_t)c3 * D + d4];
        ax += w0*v0.x + w1*v1.x + w2*v2.x + w3*v3.x;
        ay += w0*v0.y + w1*v1.y + w2*v2.y + w3*v3.y;
        az += w0*v0.z + w1*v1.z + w2*v2.z + w3*v3.z;
        aw += w0*v0.w + w1*v1.w + w2*v2.w + w3*v3.w;
    }
    for (; i < e; ++i) {
        float w = wgt[i];
        float4 v = *(const float4*)&hin[(size_t)col[i] * D + d4];
        ax += w*v.x; ay += w*v.y; az += w*v.z; aw += w*v.w;
    }
    if (RELU) {
        ax = fmaxf(ax, 0.f); ay = fmaxf(ay, 0.f);
        az = fmaxf(az, 0.f); aw = fmaxf(aw, 0.f);
    }
    *(float4*)&hout[(size_t)row * D + d4] = make_float4(ax, ay, az, aw);
}

// ---------------------------------------------------------------------------
// recon = Z @ Z^T, symmetric lower-triangle tiles, f32x2 with PRE-DUPLICATED
// A staging (zero MOVs in mainloop: A float4 LDS yields two broadcast ulls).
//   Ad[k][2r+s] = Z[rbase+r][k]  (s=0,1)   stride AD_S floats
//   Bp[k][c]    = Z[cbase+c][k]            stride BP_S floats
// ---------------------------------------------------------------------------
#define ZT   128
#define AD_S 264   // 256 + 8 pad (16B-aligned rows)
#define BP_S 136   // 128 + 8 pad
#define ZLD  132   // mirror-bounce stride

__global__ __launch_bounds__(256, 2) void zzt_sym_kernel(
    const float* __restrict__ Z, float* __restrict__ C)
{
    extern __shared__ float sm[];
    float* Ad = sm;                        // 64 * 264 floats = 67584 B
    float* Bp = sm + Z_DIM * AD_S;         // 64 * 136 floats = 34816 B

    // triangular index -> (bx, by), bx <= by
    const int l = blockIdx.x;
    int by = (int)((sqrtf(8.0f * (float)l + 1.0f) - 1.0f) * 0.5f);
    while ((by + 1) * (by + 2) / 2 <= l) ++by;
    while (by * (by + 1) / 2 > l) --by;
    const int bx = l - by * (by + 1) / 2;

    const int tid = threadIdx.x;
    const int tx = tid & 15;
    const int ty = tid >> 4;
    const int rbase = by * ZT;
    const int cbase = bx * ZT;

    // stage: A duplicated, B transposed
    const int k4 = tx * 4;
    for (int rr = ty; rr < ZT; rr += 16) {
        float4 va = *(const float4*)&Z[(size_t)(rbase + rr) * Z_DIM + k4];
        *(ull*)&Ad[(k4+0)*AD_S + 2*rr] = dup2(va.x);
        *(ull*)&Ad[(k4+1)*AD_S + 2*rr] = dup2(va.y);
        *(ull*)&Ad[(k4+2)*AD_S + 2*rr] = dup2(va.z);
        *(ull*)&Ad[(k4+3)*AD_S + 2*rr] = dup2(va.w);
        float4 vb = *(const float4*)&Z[(size_t)(cbase + rr) * Z_DIM + k4];
        Bp[(k4+0)*BP_S + rr] = vb.x;
        Bp[(k4+1)*BP_S + rr] = vb.y;
        Bp[(k4+2)*BP_S + rr] = vb.z;
        Bp[(k4+3)*BP_S + rr] = vb.w;
    }
    __syncthreads();

    ull acc[8][4] = {};
    const int ra = ty * 8;
    const int cb = tx * 8;

    #pragma unroll 4
    for (int k = 0; k < Z_DIM; ++k) {
        // 8 pre-duplicated a-operands: 4x LDS.128, no movs
        const ulonglong2* ap = (const ulonglong2*)&Ad[k * AD_S + 2 * ra];
        ulonglong2 a01 = ap[0], a23 = ap[1], a45 = ap[2], a67 = ap[3];
        // 8 b-floats = 4 packed ulls: 2x LDS.128, no movs
        const ulonglong2* bp = (const ulonglong2*)&Bp[k * BP_S + cb];
        ulonglong2 b01 = bp[0], b23 = bp[1];
        ull a[8] = { a01.x, a01.y, a23.x, a23.y, a45.x, a45.y, a67.x, a67.y };
        ull b[4] = { b01.x, b01.y, b23.x, b23.y };
        #pragma unroll
        for (int i = 0; i < 8; ++i) {
            #pragma unroll
            for (int jp = 0; jp < 4; ++jp)
                acc[i][jp] = fma2(a[i], b[jp], acc[i][jp]);
        }
    }

    float av[8][8];
    #pragma unroll
    for (int i = 0; i < 8; ++i)
        #pragma unroll
        for (int jp = 0; jp < 4; ++jp) {
            float2 v = unpack2(acc[i][jp]);
            av[i][2*jp]   = v.x;
            av[i][2*jp+1] = v.y;
        }

    // lower-triangle tile write (coalesced float4)
    #pragma unroll
    for (int i = 0; i < 8; ++i) {
        size_t off = (size_t)(rbase + ra + i) * N_NODES + cbase + cb;
        *(float4*)&C[off]     = make_float4(av[i][0], av[i][1], av[i][2], av[i][3]);
        *(float4*)&C[off + 4] = make_float4(av[i][4], av[i][5], av[i][6], av[i][7]);
    }

    if (bx == by) return;

    // mirror via swizzled smem transpose bounce
    __syncthreads();
    float* T = sm;   // 128 * 132 = 67584 B, fits in staging footprint
    #pragma unroll
    for (int j = 0; j < 8; ++j) {
        int a = cb + j;
        int rot = a & 120;
        #pragma unroll
        for (int i = 0; i < 8; ++i) {
            int b = ra + i;
            T[a * ZLD + ((b + rot) & 127)] = av[i][j];
        }
    }
    __syncthreads();

    #pragma unroll
    for (int i = 0; i < 8; ++i) {
        int a = ty * 8 + i;
        int rot = a & 120;
        float4 v0 = *(const float4*)&T[a * ZLD + ((tx * 8     + rot) & 127)];
        float4 v1 = *(const float4*)&T[a * ZLD + ((tx * 8 + 4 + rot) & 127)];
        size_t off = (size_t)(cbase + a) * N_NODES + rbase + tx * 8;
        *(float4*)&C[off]     = v0;
        *(float4*)&C[off + 4] = v1;
    }
}

// ---------------------------------------------------------------------------
extern "C" void kernel_launch(void* const* d_in, const int* in_sizes, int n_in,
                              void* d_out, int out_size)
{
    const float* x    = (const float*)d_in[0];
    const float* w1   = (const float*)d_in[1];
    const float* w2   = (const float*)d_in[2];
    const int*   erow = (const int*)  d_in[3];
    const int*   ecol = (const int*)  d_in[4];
    const float* ew   = (const float*)d_in[5];

    float* out   = (float*)d_out;
    float* recon = out;                                   // [N, N]
    float* z     = out + (size_t)N_NODES * N_NODES;       // [N, Z_DIM]

    float *h0, *h, *p;
    cudaGetSymbolAddress((void**)&h0, g_h0);
    cudaGetSymbolAddress((void**)&h,  g_h);
    cudaGetSymbolAddress((void**)&p,  g_p);

    // 1. CSR row pointers
    rowptr_kernel<<<(N_NODES + 256) / 256, 256>>>(erow);

    // 2. h0 = x @ W1  [8192 x 256]  (512 blocks, prefetched)
    dim3 g1(HID_DIM / 64, N_NODES / 64);
    sgemm_nn<64, 64, 16, 256><<<g1, 256>>>(x, w1, h0, N_NODES, IN_DIM, HID_DIM);

    // 3. h = relu(spmm(h0))  — float4 lanes
    spmm_kernel<HID_DIM, true><<<N_NODES / 4, dim3(HID_DIM / 4, 4)>>>(h0, ecol, ew, h);

    // 4. p = h @ W2  [8192 x 64]  (revert to proven 64x64 shape + prefetch)
    dim3 g2(Z_DIM / 64, N_NODES / 64);
    sgemm_nn<64, 64, 16, 256><<<g2, 256>>>(h, w2, p, N_NODES, HID_DIM, Z_DIM);

    // 5. z = spmm(p) -> output tail
    spmm_kernel<Z_DIM, false><<<N_NODES / 16, dim3(Z_DIM / 4, 16)>>>(p, ecol, ew, z);

    // 6. recon = z @ z^T, symmetric lower-triangle grid
    const int n_tiles = N_NODES / ZT;                       // 64
    const int n_blocks = n_tiles * (n_tiles + 1) / 2;       // 2080
    const int zzt_smem = (Z_DIM * AD_S + Z_DIM * BP_S) * (int)sizeof(float); // 102400
    cudaFuncSetAttribute(zzt_sym_kernel, cudaFuncAttributeMaxDynamicSharedMemorySize, zzt_smem);
    zzt_sym_kernel<<<n_blocks, 256, zzt_smem>>>(z, recon);
}